// round 14
// baseline (speedup 1.0000x reference)
#include <cuda_runtime.h>
#include <cuda_bf16.h>

#define NVOX   262144
#define NU     65536
#define NM     (NVOX - NU)
#define C_IN   128
#define C_HID  64
#define K_OUT  20
#define TILE   64
#define MT     (NM / TILE)        // 3072 masked tiles
#define UT     (NU / TILE)        // 1024 unmasked tiles
#define SA     136                // A/B1/B3/B4 row stride (bf16 elems)
#define SH     72                 // H,d / B2,B5 row stride
#define SSTG   132                // fp32 stage row stride
#define THREADS 512

typedef unsigned int u32;
typedef unsigned short u16;

__device__ __forceinline__ float leaky(float x) {
    return fmaxf(x, 0.f) + 0.01f * fminf(x, 0.f);
}
__device__ __forceinline__ u16 f2bf(float x) {
    return __bfloat16_as_ushort(__float2bfloat16(x));
}
__device__ __forceinline__ float bf2f(u16 b) {
    return __bfloat162float(__ushort_as_bfloat16(b));
}
__device__ __forceinline__ void split2(float x0, float x1, u32& hi, u32& lo) {
    u16 h0 = f2bf(x0), h1 = f2bf(x1);
    u16 l0 = f2bf(x0 - bf2f(h0)), l1 = f2bf(x1 - bf2f(h1));
    hi = (u32)h0 | ((u32)h1 << 16);
    lo = (u32)l0 | ((u32)l1 << 16);
}
__device__ __forceinline__ u32 smem_u32(const void* p) {
    u32 a; asm("{ .reg .u64 t; cvta.to.shared.u64 t, %1; cvt.u32.u64 %0, t; }" : "=r"(a) : "l"(p));
    return a;
}
__device__ __forceinline__ void ldsm4(u32* r, u32 addr) {
    asm volatile("ldmatrix.sync.aligned.m8n8.x4.shared.b16 {%0,%1,%2,%3}, [%4];"
                 : "=r"(r[0]), "=r"(r[1]), "=r"(r[2]), "=r"(r[3]) : "r"(addr));
}
__device__ __forceinline__ void ldsm2(u32* r, u32 addr) {
    asm volatile("ldmatrix.sync.aligned.m8n8.x2.shared.b16 {%0,%1}, [%2];"
                 : "=r"(r[0]), "=r"(r[1]) : "r"(addr));
}
__device__ __forceinline__ void mmab(float* c, const u32* a, u32 b0, u32 b1) {
    asm volatile("mma.sync.aligned.m16n8k16.row.col.f32.bf16.bf16.f32 "
                 "{%0,%1,%2,%3}, {%4,%5,%6,%7}, {%8,%9}, {%0,%1,%2,%3};"
                 : "+f"(c[0]), "+f"(c[1]), "+f"(c[2]), "+f"(c[3])
                 : "r"(a[0]), "r"(a[1]), "r"(a[2]), "r"(a[3]), "r"(b0), "r"(b1));
}
__device__ __forceinline__ void cpa4(u32 dst, const float* src) {
    asm volatile("cp.async.ca.shared.global [%0], [%1], 4;" :: "r"(dst), "l"(src));
}
#define CP_COMMIT() asm volatile("cp.async.commit_group;" ::: "memory")
#define CP_WAIT0()  asm volatile("cp.async.wait_group 0;" ::: "memory")

__device__ float g_W23[C_HID * C_HID];
__device__ float g_b23[C_HID];

__global__ void w23_kernel(const float* __restrict__ w2, const float* __restrict__ sdb_w,
                           const float* __restrict__ b2, const float* __restrict__ sdb_b) {
    int idx = blockIdx.x * blockDim.x + threadIdx.x;
    if (idx < C_HID * C_HID) {
        int j = idx >> 6, j2 = idx & 63;
        float acc = 0.f;
        #pragma unroll 8
        for (int c = 0; c < C_IN; ++c) acc += w2[j * C_IN + c] * sdb_w[c * C_HID + j2];
        g_W23[idx] = acc;
    }
    if (idx < C_HID) {
        float acc = sdb_b[idx];
        #pragma unroll 8
        for (int c = 0; c < C_IN; ++c) acc += b2[c] * sdb_w[c * C_HID + idx];
        g_b23[idx] = acc;
    }
}

struct Group {
    float stage[TILE * SSTG];                // fp32 gather staging (cp.async dst)
    u16 Ah[TILE * SA], Al[TILE * SA];        // feats (SA); later H / d (SH)
    int   vidx[2][TILE];
    float mus[TILE], rss[TILE];
    float red1[2 * TILE], red2[2 * TILE];
};
struct SmemM {
    Group g[2];
    u16 B1h[64 * SA], B1l[64 * SA];          // w1  [j][c]
    u16 B2h[64 * SH], B2l[64 * SH];          // W23 [j2][j]
    u16 B5h[24 * SH], B5l[24 * SH];          // ssc [k][j2]
    float b1s[64], lngs[64], lnbs[64], b23s[64];
    float sscbs[24];
};
struct SmemU {
    Group g[2];
    u16 B3h[64 * SA], B3l[64 * SA];          // sdb [j][c]
    u16 B4h[24 * SA], B4l[24 * SA];          // aux [k][c]
    u16 B5h[24 * SH], B5l[24 * SH];          // ssc [k][j2]
    float sdbbs[64];
    float sscbs[24], auxbs[24];
};
#define SMEM_MAX ((int)(sizeof(SmemM) > sizeof(SmemU) ? sizeof(SmemM) : sizeof(SmemU)))

// issue cp.async gather of tile feats into group's stage; also record vidx[buf]
__device__ __forceinline__ void issue_gather(Group* g, const float* __restrict__ x3d,
                                             const int* __restrict__ idxs, int buf, int gtid) {
    const int row = gtid >> 2;
    const int cbase = (gtid & 3) * 32;
    const int gv = __ldg(&idxs[row]);
    if ((gtid & 3) == 0) g->vidx[buf][row] = gv;
    const float* src = x3d + gv;
    u32 dst = smem_u32(&g->stage[row * SSTG + cbase]);
    #pragma unroll
    for (int i = 0; i < 32; ++i)
        cpa4(dst + i * 4, src + (size_t)(cbase + i) * NVOX);
}

// convert fp32 stage -> bf16 hi/lo A buffers (stride SA)
__device__ __forceinline__ void convert_stage(Group* g, int gtid) {
    const int row = gtid >> 2;
    const int cbase = (gtid & 3) * 32;
    char* Ah = (char*)g->Ah;
    char* Al = (char*)g->Al;
    #pragma unroll
    for (int i = 0; i < 8; ++i) {
        int c = cbase + i * 4;
        float4 f = *reinterpret_cast<const float4*>(&g->stage[row * SSTG + c]);
        u32 h0, l0, h1, l1;
        split2(f.x, f.y, h0, l0);
        split2(f.z, f.w, h1, l1);
        *(u32*)(Ah + (row * SA + c) * 2)     = h0;
        *(u32*)(Ah + (row * SA + c + 2) * 2) = h1;
        *(u32*)(Al + (row * SA + c) * 2)     = l0;
        *(u32*)(Al + (row * SA + c + 2) * 2) = l1;
    }
}

__global__ void __launch_bounds__(THREADS, 1)
fused_kernel(const float* __restrict__ x3d,
             const float* __restrict__ w1,    const float* __restrict__ b1,
             const float* __restrict__ ln_g,  const float* __restrict__ ln_b,
             const float* __restrict__ sdb_w, const float* __restrict__ sdb_b,
             const float* __restrict__ ssc_w, const float* __restrict__ ssc_b,
             const float* __restrict__ aux_w, const float* __restrict__ aux_b,
             const int* __restrict__ ui,      const int* __restrict__ mi,
             float* __restrict__ out, int mblocks)
{
    extern __shared__ char smem_raw[];
    const int t = threadIdx.x;
    const int warp = t >> 5, lane = t & 31;
    const int grp = warp >> 3;               // 0 or 1
    const int gtid = t & 255;
    const int wg = warp & 7;
    const int gbar = 1 + grp;
    #define BARG() asm volatile("bar.sync %0, 256;" :: "r"(gbar) : "memory")

    // fragment geometry (within group, 8 warps)
    const int vt = wg >> 1, nh = wg & 1;
    const int v0 = vt * 16, n0 = nh * 32;
    const int qd = lane >> 3, rw = lane & 7;
    const u32 aoffA = (u32)(((v0 + rw + (qd & 1) * 8) * SA + (qd >> 1) * 8) * 2);
    const u32 aoffH = (u32)(((v0 + rw + (qd & 1) * 8) * SH + (qd >> 1) * 8) * 2);
    #define BOFF(nb, S) ((u32)((((nb) + rw + (qd >> 1) * 8) * (S) + (qd & 1) * 8) * 2))
    const int rlo = v0 + (lane >> 2), rhi = rlo + 8;
    const int q4 = lane & 3;

    float* outsem = out + (size_t)K_OUT * NVOX;

    if (blockIdx.x < mblocks) {
        // ================= MASKED ROLE =================
        SmemM* s = reinterpret_cast<SmemM*>(smem_raw);
        Group* g = &s->g[grp];
        for (int i = t; i < 64 * 128; i += THREADS) {
            int j = i & 63, c = i >> 6;
            float x = w1[c * C_HID + j];
            u16 h = f2bf(x); s->B1h[j * SA + c] = h; s->B1l[j * SA + c] = f2bf(x - bf2f(h));
        }
        for (int i = t; i < 64 * 64; i += THREADS) {
            int j2 = i & 63, j = i >> 6;
            float x = g_W23[j * C_HID + j2];
            u16 h = f2bf(x); s->B2h[j2 * SH + j] = h; s->B2l[j2 * SH + j] = f2bf(x - bf2f(h));
        }
        for (int i = t; i < 24 * SH; i += THREADS) { s->B5h[i] = 0; s->B5l[i] = 0; }
        __syncthreads();
        for (int i = t; i < 64 * K_OUT; i += THREADS) {
            int k = i % K_OUT, j = i / K_OUT;
            float x = ssc_w[j * K_OUT + k];
            u16 h = f2bf(x); s->B5h[k * SH + j] = h; s->B5l[k * SH + j] = f2bf(x - bf2f(h));
        }
        if (t < C_HID) {
            s->b1s[t] = b1[t]; s->lngs[t] = ln_g[t]; s->lnbs[t] = ln_b[t]; s->b23s[t] = g_b23[t];
        }
        if (t < 24) s->sscbs[t] = (t < K_OUT) ? ssc_b[t] : 0.f;
        __syncthreads();

        const u32 sAh = smem_u32(g->Ah), sAl = smem_u32(g->Al);
        const u32 sB1h = smem_u32(s->B1h), sB1l = smem_u32(s->B1l);
        const u32 sB2h = smem_u32(s->B2h), sB2l = smem_u32(s->B2l);
        const u32 sB5h = smem_u32(s->B5h), sB5l = smem_u32(s->B5l);
        const u32 b1h0 = sB1h + BOFF(n0, SA), b1h1 = sB1h + BOFF(n0 + 16, SA);
        const u32 b1l0 = sB1l + BOFF(n0, SA), b1l1 = sB1l + BOFF(n0 + 16, SA);
        const u32 b2h0 = sB2h + BOFF(n0, SH), b2h1 = sB2h + BOFF(n0 + 16, SH);
        const u32 b2l0 = sB2l + BOFF(n0, SH), b2l1 = sB2l + BOFF(n0 + 16, SH);
        const u32 ox2H = (u32)(((16 + rw) * SH + (qd & 1) * 8) * 2);
        const u32 b5h = nh ? (sB5h + ox2H) : (sB5h + BOFF(0, SH));
        const u32 b5l = nh ? (sB5l + ox2H) : (sB5l + BOFF(0, SH));

        const int stride = mblocks * 2;
        int tile = blockIdx.x * 2 + grp;
        int buf = 0;
        if (tile < MT) issue_gather(g, x3d, mi + tile * TILE, 0, gtid);
        CP_COMMIT();

        for (; tile < MT; tile += stride, buf ^= 1) {
            CP_WAIT0();
            BARG();
            convert_stage(g, gtid);
            BARG();
            {
                int nxt = tile + stride;
                if (nxt < MT) issue_gather(g, x3d, mi + nxt * TILE, buf ^ 1, gtid);
                CP_COMMIT();
            }

            // D1 = feats @ w1 (K=128)
            float d1[4][4] = {};
            {
                const u32 aAh = sAh + aoffA, aAl = sAl + aoffA;
                #pragma unroll
                for (int kt = 0; kt < 8; ++kt) {
                    const u32 ka = kt * 32;
                    u32 ah[4], al[4], bh[4], bl[4];
                    ldsm4(ah, aAh + ka); ldsm4(al, aAl + ka);
                    ldsm4(bh, b1h0 + ka); ldsm4(bl, b1l0 + ka);
                    mmab(d1[0], ah, bh[0], bh[1]); mmab(d1[1], ah, bh[2], bh[3]);
                    mmab(d1[0], ah, bl[0], bl[1]); mmab(d1[1], ah, bl[2], bl[3]);
                    mmab(d1[0], al, bh[0], bh[1]); mmab(d1[1], al, bh[2], bh[3]);
                    ldsm4(bh, b1h1 + ka); ldsm4(bl, b1l1 + ka);
                    mmab(d1[2], ah, bh[0], bh[1]); mmab(d1[3], ah, bh[2], bh[3]);
                    mmab(d1[2], ah, bl[0], bl[1]); mmab(d1[3], ah, bl[2], bl[3]);
                    mmab(d1[2], al, bh[0], bh[1]); mmab(d1[3], al, bh[2], bh[3]);
                }
            }
            // h = D1 + b1; LN partials
            {
                float slo = 0.f, qlo = 0.f, shi = 0.f, qhi = 0.f;
                #pragma unroll
                for (int nt = 0; nt < 4; ++nt) {
                    int j = n0 + nt * 8 + q4 * 2;
                    float bb0 = s->b1s[j], bb1 = s->b1s[j + 1];
                    d1[nt][0] += bb0; d1[nt][1] += bb1; d1[nt][2] += bb0; d1[nt][3] += bb1;
                    slo += d1[nt][0] + d1[nt][1];
                    qlo += d1[nt][0] * d1[nt][0] + d1[nt][1] * d1[nt][1];
                    shi += d1[nt][2] + d1[nt][3];
                    qhi += d1[nt][2] * d1[nt][2] + d1[nt][3] * d1[nt][3];
                }
                #pragma unroll
                for (int o = 1; o < 4; o <<= 1) {
                    slo += __shfl_xor_sync(0xFFFFFFFFu, slo, o);
                    qlo += __shfl_xor_sync(0xFFFFFFFFu, qlo, o);
                    shi += __shfl_xor_sync(0xFFFFFFFFu, shi, o);
                    qhi += __shfl_xor_sync(0xFFFFFFFFu, qhi, o);
                }
                if (q4 == 0) {
                    g->red1[nh * TILE + rlo] = slo; g->red2[nh * TILE + rlo] = qlo;
                    g->red1[nh * TILE + rhi] = shi; g->red2[nh * TILE + rhi] = qhi;
                }
            }
            BARG();
            if (gtid < TILE) {
                float su = g->red1[gtid] + g->red1[TILE + gtid];
                float sq = g->red2[gtid] + g->red2[TILE + gtid];
                float mu = su * (1.f / 64.f);
                float var = sq * (1.f / 64.f) - mu * mu;
                g->mus[gtid] = mu; g->rss[gtid] = rsqrtf(var + 1e-5f);
            }
            BARG();
            // normalize + leaky -> H (SH)
            {
                float mu0 = g->mus[rlo], rs0 = g->rss[rlo];
                float mu1 = g->mus[rhi], rs1 = g->rss[rhi];
                #pragma unroll
                for (int nt = 0; nt < 4; ++nt) {
                    int j = n0 + nt * 8 + q4 * 2;
                    float g0 = s->lngs[j], g1 = s->lngs[j + 1];
                    float c0 = s->lnbs[j], c1 = s->lnbs[j + 1];
                    float x0 = leaky((d1[nt][0] - mu0) * rs0 * g0 + c0);
                    float x1 = leaky((d1[nt][1] - mu0) * rs0 * g1 + c1);
                    float x2 = leaky((d1[nt][2] - mu1) * rs1 * g0 + c0);
                    float x3 = leaky((d1[nt][3] - mu1) * rs1 * g1 + c1);
                    u32 hi, lo;
                    split2(x0, x1, hi, lo);
                    *(u32*)((char*)g->Ah + (rlo * SH + j) * 2) = hi;
                    *(u32*)((char*)g->Al + (rlo * SH + j) * 2) = lo;
                    split2(x2, x3, hi, lo);
                    *(u32*)((char*)g->Ah + (rhi * SH + j) * 2) = hi;
                    *(u32*)((char*)g->Al + (rhi * SH + j) * 2) = lo;
                }
            }
            BARG();
            // D2 = H @ W23 (K=64)
            float d2[4][4] = {};
            {
                const u32 aHh = sAh + aoffH, aHl = sAl + aoffH;
                #pragma unroll
                for (int kt = 0; kt < 4; ++kt) {
                    const u32 ka = kt * 32;
                    u32 ah[4], al[4], bh[4], bl[4];
                    ldsm4(ah, aHh + ka); ldsm4(al, aHl + ka);
                    ldsm4(bh, b2h0 + ka); ldsm4(bl, b2l0 + ka);
                    mmab(d2[0], ah, bh[0], bh[1]); mmab(d2[1], ah, bh[2], bh[3]);
                    mmab(d2[0], ah, bl[0], bl[1]); mmab(d2[1], ah, bl[2], bl[3]);
                    mmab(d2[0], al, bh[0], bh[1]); mmab(d2[1], al, bh[2], bh[3]);
                    ldsm4(bh, b2h1 + ka); ldsm4(bl, b2l1 + ka);
                    mmab(d2[2], ah, bh[0], bh[1]); mmab(d2[3], ah, bh[2], bh[3]);
                    mmab(d2[2], ah, bl[0], bl[1]); mmab(d2[3], ah, bl[2], bl[3]);
                    mmab(d2[2], al, bh[0], bh[1]); mmab(d2[3], al, bh[2], bh[3]);
                }
            }
            BARG();
            // d = leaky(D2 + b23) -> bf16 in place
            {
                #pragma unroll
                for (int nt = 0; nt < 4; ++nt) {
                    int j = n0 + nt * 8 + q4 * 2;
                    float bm0 = s->b23s[j], bm1 = s->b23s[j + 1];
                    float x0 = leaky(d2[nt][0] + bm0);
                    float x1 = leaky(d2[nt][1] + bm1);
                    float x2 = leaky(d2[nt][2] + bm0);
                    float x3 = leaky(d2[nt][3] + bm1);
                    u32 hi, lo;
                    split2(x0, x1, hi, lo);
                    *(u32*)((char*)g->Ah + (rlo * SH + j) * 2) = hi;
                    *(u32*)((char*)g->Al + (rlo * SH + j) * 2) = lo;
                    split2(x2, x3, hi, lo);
                    *(u32*)((char*)g->Ah + (rhi * SH + j) * 2) = hi;
                    *(u32*)((char*)g->Al + (rhi * SH + j) * 2) = lo;
                }
            }
            BARG();
            // D5 = d @ ssc (K=64)
            float d5[2][4] = {};
            {
                const u32 aHh = sAh + aoffH, aHl = sAl + aoffH;
                #pragma unroll
                for (int kt = 0; kt < 4; ++kt) {
                    const u32 ka = kt * 32;
                    u32 ah[4], al[4], bh[4], bl[4];
                    ldsm4(ah, aHh + ka); ldsm4(al, aHl + ka);
                    if (nh == 0) {
                        ldsm4(bh, b5h + ka); ldsm4(bl, b5l + ka);
                        mmab(d5[0], ah, bh[0], bh[1]); mmab(d5[1], ah, bh[2], bh[3]);
                        mmab(d5[0], ah, bl[0], bl[1]); mmab(d5[1], ah, bl[2], bl[3]);
                        mmab(d5[0], al, bh[0], bh[1]); mmab(d5[1], al, bh[2], bh[3]);
                    } else {
                        ldsm2(bh, b5h + ka); ldsm2(bl, b5l + ka);
                        mmab(d5[0], ah, bh[0], bh[1]);
                        mmab(d5[0], ah, bl[0], bl[1]);
                        mmab(d5[0], al, bh[0], bh[1]);
                    }
                }
            }
            {
                const int vlo = g->vidx[buf][rlo], vhi = g->vidx[buf][rhi];
                if (nh == 0) {
                    #pragma unroll
                    for (int nt = 0; nt < 2; ++nt) {
                        int k = nt * 8 + q4 * 2;
                        out[(size_t)k       * NVOX + vlo] = d5[nt][0] + s->sscbs[k];
                        out[(size_t)(k + 1) * NVOX + vlo] = d5[nt][1] + s->sscbs[k + 1];
                        out[(size_t)k       * NVOX + vhi] = d5[nt][2] + s->sscbs[k];
                        out[(size_t)(k + 1) * NVOX + vhi] = d5[nt][3] + s->sscbs[k + 1];
                    }
                } else {
                    int k = 16 + q4 * 2;
                    if (k < K_OUT) {
                        out[(size_t)k       * NVOX + vlo] = d5[0][0] + s->sscbs[k];
                        out[(size_t)(k + 1) * NVOX + vlo] = d5[0][1] + s->sscbs[k + 1];
                        out[(size_t)k       * NVOX + vhi] = d5[0][2] + s->sscbs[k];
                        out[(size_t)(k + 1) * NVOX + vhi] = d5[0][3] + s->sscbs[k + 1];
                    }
                }
            }
            BARG();                          // d reads done before next convert
        }
    } else {
        // ================= UNMASKED ROLE =================
        SmemU* s = reinterpret_cast<SmemU*>(smem_raw);
        Group* g = &s->g[grp];
        const int ublocks = gridDim.x - mblocks;
        for (int i = t; i < 24 * SA; i += THREADS) { s->B4h[i] = 0; s->B4l[i] = 0; }
        for (int i = t; i < 24 * SH; i += THREADS) { s->B5h[i] = 0; s->B5l[i] = 0; }
        __syncthreads();
        for (int i = t; i < 64 * 128; i += THREADS) {
            int j = i & 63, c = i >> 6;
            float x = sdb_w[c * C_HID + j];
            u16 h = f2bf(x); s->B3h[j * SA + c] = h; s->B3l[j * SA + c] = f2bf(x - bf2f(h));
        }
        for (int i = t; i < K_OUT * 128; i += THREADS) {
            int k = i % K_OUT, c = i / K_OUT;
            float x = aux_w[c * K_OUT + k];
            u16 h = f2bf(x); s->B4h[k * SA + c] = h; s->B4l[k * SA + c] = f2bf(x - bf2f(h));
        }
        for (int i = t; i < 64 * K_OUT; i += THREADS) {
            int k = i % K_OUT, j = i / K_OUT;
            float x = ssc_w[j * K_OUT + k];
            u16 h = f2bf(x); s->B5h[k * SH + j] = h; s->B5l[k * SH + j] = f2bf(x - bf2f(h));
        }
        if (t < C_HID) s->sdbbs[t] = sdb_b[t];
        if (t < 24) { s->sscbs[t] = (t < K_OUT) ? ssc_b[t] : 0.f;
                      s->auxbs[t] = (t < K_OUT) ? aux_b[t] : 0.f; }
        __syncthreads();

        const u32 sAh = smem_u32(g->Ah), sAl = smem_u32(g->Al);
        const u32 sB3h = smem_u32(s->B3h), sB3l = smem_u32(s->B3l);
        const u32 sB4h = smem_u32(s->B4h), sB4l = smem_u32(s->B4l);
        const u32 sB5h = smem_u32(s->B5h), sB5l = smem_u32(s->B5l);
        const u32 b3h0 = sB3h + BOFF(n0, SA), b3h1 = sB3h + BOFF(n0 + 16, SA);
        const u32 b3l0 = sB3l + BOFF(n0, SA), b3l1 = sB3l + BOFF(n0 + 16, SA);
        const u32 ox2 = (u32)(((16 + rw) * SA + (qd & 1) * 8) * 2);
        const u32 b4h = nh ? (sB4h + ox2) : (sB4h + BOFF(0, SA));
        const u32 b4l = nh ? (sB4l + ox2) : (sB4l + BOFF(0, SA));
        const u32 ox2H = (u32)(((16 + rw) * SH + (qd & 1) * 8) * 2);
        const u32 b5h = nh ? (sB5h + ox2H) : (sB5h + BOFF(0, SH));
        const u32 b5l = nh ? (sB5l + ox2H) : (sB5l + BOFF(0, SH));

        const int stride = ublocks * 2;
        int tile = (blockIdx.x - mblocks) * 2 + grp;
        int buf = 0;
        if (tile < UT) issue_gather(g, x3d, ui + tile * TILE, 0, gtid);
        CP_COMMIT();

        for (; tile < UT; tile += stride, buf ^= 1) {
            CP_WAIT0();
            BARG();
            convert_stage(g, gtid);
            BARG();
            {
                int nxt = tile + stride;
                if (nxt < UT) issue_gather(g, x3d, ui + nxt * TILE, buf ^ 1, gtid);
                CP_COMMIT();
            }

            // D3 = feats @ sdb, D4 = feats @ aux (K=128)
            float d3[4][4] = {}, d4[2][4] = {};
            {
                const u32 aAh = sAh + aoffA, aAl = sAl + aoffA;
                #pragma unroll
                for (int kt = 0; kt < 8; ++kt) {
                    const u32 ka = kt * 32;
                    u32 ah[4], al[4], bh[4], bl[4];
                    ldsm4(ah, aAh + ka); ldsm4(al, aAl + ka);
                    ldsm4(bh, b3h0 + ka); ldsm4(bl, b3l0 + ka);
                    mmab(d3[0], ah, bh[0], bh[1]); mmab(d3[1], ah, bh[2], bh[3]);
                    mmab(d3[0], ah, bl[0], bl[1]); mmab(d3[1], ah, bl[2], bl[3]);
                    mmab(d3[0], al, bh[0], bh[1]); mmab(d3[1], al, bh[2], bh[3]);
                    ldsm4(bh, b3h1 + ka); ldsm4(bl, b3l1 + ka);
                    mmab(d3[2], ah, bh[0], bh[1]); mmab(d3[3], ah, bh[2], bh[3]);
                    mmab(d3[2], ah, bl[0], bl[1]); mmab(d3[3], ah, bl[2], bl[3]);
                    mmab(d3[2], al, bh[0], bh[1]); mmab(d3[3], al, bh[2], bh[3]);
                    if (nh == 0) {
                        ldsm4(bh, b4h + ka); ldsm4(bl, b4l + ka);
                        mmab(d4[0], ah, bh[0], bh[1]); mmab(d4[1], ah, bh[2], bh[3]);
                        mmab(d4[0], ah, bl[0], bl[1]); mmab(d4[1], ah, bl[2], bl[3]);
                        mmab(d4[0], al, bh[0], bh[1]); mmab(d4[1], al, bh[2], bh[3]);
                    } else {
                        ldsm2(bh, b4h + ka); ldsm2(bl, b4l + ka);
                        mmab(d4[0], ah, bh[0], bh[1]);
                        mmab(d4[0], ah, bl[0], bl[1]);
                        mmab(d4[0], al, bh[0], bh[1]);
                    }
                }
            }
            // AUX writeback: rank = tile*64 + row
            {
                const int rbase = tile * TILE;
                int r0v = rbase + rlo, r1v = rbase + rhi;
                if (nh == 0) {
                    #pragma unroll
                    for (int nt = 0; nt < 2; ++nt) {
                        int k = nt * 8 + q4 * 2;
                        *(float2*)&outsem[(size_t)r0v * K_OUT + k] =
                            make_float2(d4[nt][0] + s->auxbs[k], d4[nt][1] + s->auxbs[k + 1]);
                        *(float2*)&outsem[(size_t)r1v * K_OUT + k] =
                            make_float2(d4[nt][2] + s->auxbs[k], d4[nt][3] + s->auxbs[k + 1]);
                    }
                } else {
                    int k = 16 + q4 * 2;
                    if (k < K_OUT) {
                        *(float2*)&outsem[(size_t)r0v * K_OUT + k] =
                            make_float2(d4[0][0] + s->auxbs[k], d4[0][1] + s->auxbs[k + 1]);
                        *(float2*)&outsem[(size_t)r1v * K_OUT + k] =
                            make_float2(d4[0][2] + s->auxbs[k], d4[0][3] + s->auxbs[k + 1]);
                    }
                }
            }
            BARG();                          // feats(SA) reads done before SH overwrite
            // d = leaky(D3 + sdb_b) -> bf16 in place
            {
                #pragma unroll
                for (int nt = 0; nt < 4; ++nt) {
                    int j = n0 + nt * 8 + q4 * 2;
                    float bu0 = s->sdbbs[j], bu1 = s->sdbbs[j + 1];
                    float x0 = leaky(d3[nt][0] + bu0);
                    float x1 = leaky(d3[nt][1] + bu1);
                    float x2 = leaky(d3[nt][2] + bu0);
                    float x3 = leaky(d3[nt][3] + bu1);
                    u32 hi, lo;
                    split2(x0, x1, hi, lo);
                    *(u32*)((char*)g->Ah + (rlo * SH + j) * 2) = hi;
                    *(u32*)((char*)g->Al + (rlo * SH + j) * 2) = lo;
                    split2(x2, x3, hi, lo);
                    *(u32*)((char*)g->Ah + (rhi * SH + j) * 2) = hi;
                    *(u32*)((char*)g->Al + (rhi * SH + j) * 2) = lo;
                }
            }
            BARG();
            // D5 = d @ ssc (K=64)
            float d5[2][4] = {};
            {
                const u32 aHh = sAh + aoffH, aHl = sAl + aoffH;
                #pragma unroll
                for (int kt = 0; kt < 4; ++kt) {
                    const u32 ka = kt * 32;
                    u32 ah[4], al[4], bh[4], bl[4];
                    ldsm4(ah, aHh + ka); ldsm4(al, aHl + ka);
                    if (nh == 0) {
                        ldsm4(bh, b5h + ka); ldsm4(bl, b5l + ka);
                        mmab(d5[0], ah, bh[0], bh[1]); mmab(d5[1], ah, bh[2], bh[3]);
                        mmab(d5[0], ah, bl[0], bl[1]); mmab(d5[1], ah, bl[2], bl[3]);
                        mmab(d5[0], al, bh[0], bh[1]); mmab(d5[1], al, bh[2], bh[3]);
                    } else {
                        ldsm2(bh, b5h + ka); ldsm2(bl, b5l + ka);
                        mmab(d5[0], ah, bh[0], bh[1]);
                        mmab(d5[0], ah, bl[0], bl[1]);
                        mmab(d5[0], al, bh[0], bh[1]);
                    }
                }
            }
            {
                const int vlo = g->vidx[buf][rlo], vhi = g->vidx[buf][rhi];
                if (nh == 0) {
                    #pragma unroll
                    for (int nt = 0; nt < 2; ++nt) {
                        int k = nt * 8 + q4 * 2;
                        out[(size_t)k       * NVOX + vlo] = d5[nt][0] + s->sscbs[k];
                        out[(size_t)(k + 1) * NVOX + vlo] = d5[nt][1] + s->sscbs[k + 1];
                        out[(size_t)k       * NVOX + vhi] = d5[nt][2] + s->sscbs[k];
                        out[(size_t)(k + 1) * NVOX + vhi] = d5[nt][3] + s->sscbs[k + 1];
                    }
                } else {
                    int k = 16 + q4 * 2;
                    if (k < K_OUT) {
                        out[(size_t)k       * NVOX + vlo] = d5[0][0] + s->sscbs[k];
                        out[(size_t)(k + 1) * NVOX + vlo] = d5[0][1] + s->sscbs[k + 1];
                        out[(size_t)k       * NVOX + vhi] = d5[0][2] + s->sscbs[k];
                        out[(size_t)(k + 1) * NVOX + vhi] = d5[0][3] + s->sscbs[k + 1];
                    }
                }
            }
            BARG();                          // d reads done before next convert
        }
    }
}

extern "C" void kernel_launch(void* const* d_in, const int* in_sizes, int n_in,
                              void* d_out, int out_size)
{
    const float* x3d   = (const float*)d_in[0];
    const float* w1    = (const float*)d_in[1];
    const float* b1    = (const float*)d_in[2];
    const float* ln_g  = (const float*)d_in[3];
    const float* ln_b  = (const float*)d_in[4];
    const float* w2    = (const float*)d_in[5];
    const float* b2    = (const float*)d_in[6];
    const float* sdb_w = (const float*)d_in[7];
    const float* sdb_b = (const float*)d_in[8];
    const float* ssc_w = (const float*)d_in[9];
    const float* ssc_b = (const float*)d_in[10];
    const float* aux_w = (const float*)d_in[11];
    const float* aux_b = (const float*)d_in[12];
    const int* ui      = (const int*)d_in[13];
    const int* mi      = (const int*)d_in[14];
    float* out         = (float*)d_out;

    int nsm = 0;
    cudaDeviceGetAttribute(&nsm, cudaDevAttrMultiProcessorCount, 0);
    if (nsm <= 0) nsm = 148;

    int blocks  = nsm;
    int mblocks = (blocks * 3) / 4;       // 3:1 masked:unmasked tile ratio

    cudaFuncSetAttribute(fused_kernel,
                         cudaFuncAttributeMaxDynamicSharedMemorySize, SMEM_MAX);

    w23_kernel<<<16, 256>>>(w2, sdb_w, b2, sdb_b);
    fused_kernel<<<blocks, THREADS, SMEM_MAX>>>(x3d, w1, b1, ln_g, ln_b,
                                                sdb_w, sdb_b, ssc_w, ssc_b,
                                                aux_w, aux_b, ui, mi, out, mblocks);
}

// round 15
// speedup vs baseline: 1.3215x; 1.3215x over previous
#include <cuda_runtime.h>
#include <cuda_bf16.h>

#define NVOX   262144
#define NU     65536
#define NM     (NVOX - NU)
#define C_IN   128
#define C_HID  64
#define K_OUT  20
#define TILE   64
#define MT     (NM / TILE)        // 3072 masked tiles
#define UT     (NU / TILE)        // 1024 unmasked tiles
#define SA     136                // feats/B1/B3/B4 row stride (bf16 elems)
#define SH     72                 // H,d / B2,B5 row stride
#define THREADS 256

typedef unsigned int u32;
typedef unsigned short u16;

__device__ __forceinline__ float leaky(float x) {
    return fmaxf(x, 0.f) + 0.01f * fminf(x, 0.f);
}
__device__ __forceinline__ u16 f2bf(float x) {
    return __bfloat16_as_ushort(__float2bfloat16(x));
}
__device__ __forceinline__ float bf2f(u16 b) {
    return __bfloat162float(__ushort_as_bfloat16(b));
}
__device__ __forceinline__ void split2(float x0, float x1, u32& hi, u32& lo) {
    u16 h0 = f2bf(x0), h1 = f2bf(x1);
    u16 l0 = f2bf(x0 - bf2f(h0)), l1 = f2bf(x1 - bf2f(h1));
    hi = (u32)h0 | ((u32)h1 << 16);
    lo = (u32)l0 | ((u32)l1 << 16);
}
__device__ __forceinline__ u32 smem_u32(const void* p) {
    u32 a; asm("{ .reg .u64 t; cvta.to.shared.u64 t, %1; cvt.u32.u64 %0, t; }" : "=r"(a) : "l"(p));
    return a;
}
__device__ __forceinline__ void ldsm4(u32* r, u32 addr) {
    asm volatile("ldmatrix.sync.aligned.m8n8.x4.shared.b16 {%0,%1,%2,%3}, [%4];"
                 : "=r"(r[0]), "=r"(r[1]), "=r"(r[2]), "=r"(r[3]) : "r"(addr));
}
__device__ __forceinline__ void ldsm2(u32* r, u32 addr) {
    asm volatile("ldmatrix.sync.aligned.m8n8.x2.shared.b16 {%0,%1}, [%2];"
                 : "=r"(r[0]), "=r"(r[1]) : "r"(addr));
}
__device__ __forceinline__ void mmab(float* c, const u32* a, u32 b0, u32 b1) {
    asm volatile("mma.sync.aligned.m16n8k16.row.col.f32.bf16.bf16.f32 "
                 "{%0,%1,%2,%3}, {%4,%5,%6,%7}, {%8,%9}, {%0,%1,%2,%3};"
                 : "+f"(c[0]), "+f"(c[1]), "+f"(c[2]), "+f"(c[3])
                 : "r"(a[0]), "r"(a[1]), "r"(a[2]), "r"(a[3]), "r"(b0), "r"(b1));
}

__device__ float g_W23[C_HID * C_HID];
__device__ float g_b23[C_HID];
__device__ int   g_mctr;
__device__ int   g_uctr;

__global__ void w23_kernel(const float* __restrict__ w2, const float* __restrict__ sdb_w,
                           const float* __restrict__ b2, const float* __restrict__ sdb_b) {
    int idx = blockIdx.x * blockDim.x + threadIdx.x;
    if (idx == 0) { g_mctr = 0; g_uctr = 0; }       // reset work-steal counters each launch
    if (idx < C_HID * C_HID) {
        int j = idx >> 6, j2 = idx & 63;
        float acc = 0.f;
        #pragma unroll 8
        for (int c = 0; c < C_IN; ++c) acc += w2[j * C_IN + c] * sdb_w[c * C_HID + j2];
        g_W23[idx] = acc;
    }
    if (idx < C_HID) {
        float acc = sdb_b[idx];
        #pragma unroll 8
        for (int c = 0; c < C_IN; ++c) acc += b2[c] * sdb_w[c * C_HID + idx];
        g_b23[idx] = acc;
    }
}

struct SmemM {                              // masked role
    u16 Ah[TILE * SA], Al[TILE * SA];       // feats (SA); later H / d (SH)
    u16 B1h[64 * SA], B1l[64 * SA];         // w1  [j][c]
    u16 B2h[64 * SH], B2l[64 * SH];         // W23 [j2][j]
    u16 B5h[24 * SH], B5l[24 * SH];         // ssc [k][j2]
    float b1s[64], lngs[64], lnbs[64], b23s[64];
    float sscbs[24];
    float mus[TILE], rss[TILE];
    float red1[2 * TILE], red2[2 * TILE];
    int   vidx[TILE];
    int   nxt;
};
struct SmemU {                              // unmasked role
    u16 Ah[TILE * SA], Al[TILE * SA];
    u16 B3h[64 * SA], B3l[64 * SA];         // sdb [j][c]
    u16 B4h[24 * SA], B4l[24 * SA];         // aux [k][c]
    u16 B5h[24 * SH], B5l[24 * SH];         // ssc [k][j2]
    float sdbbs[64];
    float sscbs[24], auxbs[24];
    int   vidx[TILE];
    int   nxt;
};
#define SMEM_MAX ((int)(sizeof(SmemM) > sizeof(SmemU) ? sizeof(SmemM) : sizeof(SmemU)))

__global__ void __launch_bounds__(THREADS, 2)
fused_kernel(const float* __restrict__ x3d,
             const float* __restrict__ w1,    const float* __restrict__ b1,
             const float* __restrict__ ln_g,  const float* __restrict__ ln_b,
             const float* __restrict__ sdb_w, const float* __restrict__ sdb_b,
             const float* __restrict__ ssc_w, const float* __restrict__ ssc_b,
             const float* __restrict__ aux_w, const float* __restrict__ aux_b,
             const int* __restrict__ ui,      const int* __restrict__ mi,
             float* __restrict__ out, int mblocks)
{
    extern __shared__ char smem_raw[];
    const int t = threadIdx.x;
    const int warp = t >> 5, lane = t & 31;

    // fragment geometry (role-independent)
    const int vt = warp >> 1, nh = warp & 1;
    const int v0 = vt * 16, n0 = nh * 32;
    const int qd = lane >> 3, rw = lane & 7;
    const u32 aoffA = (u32)(((v0 + rw + (qd & 1) * 8) * SA + (qd >> 1) * 8) * 2);
    const u32 aoffH = (u32)(((v0 + rw + (qd & 1) * 8) * SH + (qd >> 1) * 8) * 2);
    #define BOFF(nb, S) ((u32)((((nb) + rw + (qd >> 1) * 8) * (S) + (qd & 1) * 8) * 2))
    const int rlo = v0 + (lane >> 2), rhi = rlo + 8;
    const int q4 = lane & 3;
    const int lv = warp * 8 + (lane & 7);       // loader row 0..63
    const int lcq = (lane >> 3) * 2;

    float* outsem = out + (size_t)K_OUT * NVOX;

    if (blockIdx.x < mblocks) {
        // ================= MASKED ROLE =================
        SmemM* s = reinterpret_cast<SmemM*>(smem_raw);
        for (int i = t; i < 64 * 128; i += THREADS) {
            int j = i & 63, c = i >> 6;
            float x = w1[c * C_HID + j];
            u16 h = f2bf(x); s->B1h[j * SA + c] = h; s->B1l[j * SA + c] = f2bf(x - bf2f(h));
        }
        for (int i = t; i < 64 * 64; i += THREADS) {
            int j2 = i & 63, j = i >> 6;
            float x = g_W23[j * C_HID + j2];
            u16 h = f2bf(x); s->B2h[j2 * SH + j] = h; s->B2l[j2 * SH + j] = f2bf(x - bf2f(h));
        }
        for (int i = t; i < 24 * SH; i += THREADS) { s->B5h[i] = 0; s->B5l[i] = 0; }
        __syncthreads();
        for (int i = t; i < 64 * K_OUT; i += THREADS) {
            int k = i % K_OUT, j = i / K_OUT;
            float x = ssc_w[j * K_OUT + k];
            u16 h = f2bf(x); s->B5h[k * SH + j] = h; s->B5l[k * SH + j] = f2bf(x - bf2f(h));
        }
        if (t < C_HID) {
            s->b1s[t] = b1[t]; s->lngs[t] = ln_g[t]; s->lnbs[t] = ln_b[t]; s->b23s[t] = g_b23[t];
        }
        if (t < 24) s->sscbs[t] = (t < K_OUT) ? ssc_b[t] : 0.f;

        const u32 sAh = smem_u32(s->Ah), sAl = smem_u32(s->Al);
        const u32 sB1h = smem_u32(s->B1h), sB1l = smem_u32(s->B1l);
        const u32 sB2h = smem_u32(s->B2h), sB2l = smem_u32(s->B2l);
        const u32 sB5h = smem_u32(s->B5h), sB5l = smem_u32(s->B5l);
        const u32 b1h0 = sB1h + BOFF(n0, SA), b1h1 = sB1h + BOFF(n0 + 16, SA);
        const u32 b1l0 = sB1l + BOFF(n0, SA), b1l1 = sB1l + BOFF(n0 + 16, SA);
        const u32 b2h0 = sB2h + BOFF(n0, SH), b2h1 = sB2h + BOFF(n0 + 16, SH);
        const u32 b2l0 = sB2l + BOFF(n0, SH), b2l1 = sB2l + BOFF(n0 + 16, SH);
        const u32 ox2H = (u32)(((16 + rw) * SH + (qd & 1) * 8) * 2);
        const u32 b5h = nh ? (sB5h + ox2H) : (sB5h + BOFF(0, SH));
        const u32 b5l = nh ? (sB5l + ox2H) : (sB5l + BOFF(0, SH));

        for (;;) {
            __syncthreads();                 // prior tile fully consumed; protects nxt
            if (t == 0) s->nxt = atomicAdd(&g_mctr, 1);
            __syncthreads();
            const int tile = s->nxt;
            if (tile >= MT) break;
            const int* idxs = mi + tile * TILE;
            {
                const int gv = __ldg(&idxs[lv]);
                #pragma unroll 4
                for (int i = 0; i < 16; ++i) {
                    int c = i * 8 + lcq;
                    float f0 = x3d[(size_t)c * NVOX + gv];
                    float f1 = x3d[(size_t)(c + 1) * NVOX + gv];
                    u32 hi, lo; split2(f0, f1, hi, lo);
                    *(u32*)((char*)s->Ah + (lv * SA + c) * 2) = hi;
                    *(u32*)((char*)s->Al + (lv * SA + c) * 2) = lo;
                }
            }
            if (t < TILE) s->vidx[t] = idxs[t];
            __syncthreads();

            // D1 = feats @ w1 (K=128)
            float d1[4][4] = {};
            {
                const u32 aAh = sAh + aoffA, aAl = sAl + aoffA;
                #pragma unroll
                for (int kt = 0; kt < 8; ++kt) {
                    const u32 ka = kt * 32;
                    u32 ah[4], al[4], bh[4], bl[4];
                    ldsm4(ah, aAh + ka); ldsm4(al, aAl + ka);
                    ldsm4(bh, b1h0 + ka); ldsm4(bl, b1l0 + ka);
                    mmab(d1[0], ah, bh[0], bh[1]); mmab(d1[1], ah, bh[2], bh[3]);
                    mmab(d1[0], ah, bl[0], bl[1]); mmab(d1[1], ah, bl[2], bl[3]);
                    mmab(d1[0], al, bh[0], bh[1]); mmab(d1[1], al, bh[2], bh[3]);
                    ldsm4(bh, b1h1 + ka); ldsm4(bl, b1l1 + ka);
                    mmab(d1[2], ah, bh[0], bh[1]); mmab(d1[3], ah, bh[2], bh[3]);
                    mmab(d1[2], ah, bl[0], bl[1]); mmab(d1[3], ah, bl[2], bl[3]);
                    mmab(d1[2], al, bh[0], bh[1]); mmab(d1[3], al, bh[2], bh[3]);
                }
            }
            // h = D1 + b1; LN partials
            {
                float slo = 0.f, qlo = 0.f, shi = 0.f, qhi = 0.f;
                #pragma unroll
                for (int nt = 0; nt < 4; ++nt) {
                    int j = n0 + nt * 8 + q4 * 2;
                    float bb0 = s->b1s[j], bb1 = s->b1s[j + 1];
                    d1[nt][0] += bb0; d1[nt][1] += bb1; d1[nt][2] += bb0; d1[nt][3] += bb1;
                    slo += d1[nt][0] + d1[nt][1];
                    qlo += d1[nt][0] * d1[nt][0] + d1[nt][1] * d1[nt][1];
                    shi += d1[nt][2] + d1[nt][3];
                    qhi += d1[nt][2] * d1[nt][2] + d1[nt][3] * d1[nt][3];
                }
                #pragma unroll
                for (int o = 1; o < 4; o <<= 1) {
                    slo += __shfl_xor_sync(0xFFFFFFFFu, slo, o);
                    qlo += __shfl_xor_sync(0xFFFFFFFFu, qlo, o);
                    shi += __shfl_xor_sync(0xFFFFFFFFu, shi, o);
                    qhi += __shfl_xor_sync(0xFFFFFFFFu, qhi, o);
                }
                if (q4 == 0) {
                    s->red1[nh * TILE + rlo] = slo; s->red2[nh * TILE + rlo] = qlo;
                    s->red1[nh * TILE + rhi] = shi; s->red2[nh * TILE + rhi] = qhi;
                }
            }
            __syncthreads();
            if (t < TILE) {
                float su = s->red1[t] + s->red1[TILE + t];
                float sq = s->red2[t] + s->red2[TILE + t];
                float mu = su * (1.f / 64.f);
                float var = sq * (1.f / 64.f) - mu * mu;
                s->mus[t] = mu; s->rss[t] = rsqrtf(var + 1e-5f);
            }
            __syncthreads();
            // normalize + leaky -> H (SH)
            {
                float mu0 = s->mus[rlo], rs0 = s->rss[rlo];
                float mu1 = s->mus[rhi], rs1 = s->rss[rhi];
                #pragma unroll
                for (int nt = 0; nt < 4; ++nt) {
                    int j = n0 + nt * 8 + q4 * 2;
                    float g0 = s->lngs[j], g1 = s->lngs[j + 1];
                    float c0 = s->lnbs[j], c1 = s->lnbs[j + 1];
                    float x0 = leaky((d1[nt][0] - mu0) * rs0 * g0 + c0);
                    float x1 = leaky((d1[nt][1] - mu0) * rs0 * g1 + c1);
                    float x2 = leaky((d1[nt][2] - mu1) * rs1 * g0 + c0);
                    float x3 = leaky((d1[nt][3] - mu1) * rs1 * g1 + c1);
                    u32 hi, lo;
                    split2(x0, x1, hi, lo);
                    *(u32*)((char*)s->Ah + (rlo * SH + j) * 2) = hi;
                    *(u32*)((char*)s->Al + (rlo * SH + j) * 2) = lo;
                    split2(x2, x3, hi, lo);
                    *(u32*)((char*)s->Ah + (rhi * SH + j) * 2) = hi;
                    *(u32*)((char*)s->Al + (rhi * SH + j) * 2) = lo;
                }
            }
            __syncthreads();
            // D2 = H @ W23 (K=64)
            float d2[4][4] = {};
            {
                const u32 aHh = sAh + aoffH, aHl = sAl + aoffH;
                #pragma unroll
                for (int kt = 0; kt < 4; ++kt) {
                    const u32 ka = kt * 32;
                    u32 ah[4], al[4], bh[4], bl[4];
                    ldsm4(ah, aHh + ka); ldsm4(al, aHl + ka);
                    ldsm4(bh, b2h0 + ka); ldsm4(bl, b2l0 + ka);
                    mmab(d2[0], ah, bh[0], bh[1]); mmab(d2[1], ah, bh[2], bh[3]);
                    mmab(d2[0], ah, bl[0], bl[1]); mmab(d2[1], ah, bl[2], bl[3]);
                    mmab(d2[0], al, bh[0], bh[1]); mmab(d2[1], al, bh[2], bh[3]);
                    ldsm4(bh, b2h1 + ka); ldsm4(bl, b2l1 + ka);
                    mmab(d2[2], ah, bh[0], bh[1]); mmab(d2[3], ah, bh[2], bh[3]);
                    mmab(d2[2], ah, bl[0], bl[1]); mmab(d2[3], ah, bl[2], bl[3]);
                    mmab(d2[2], al, bh[0], bh[1]); mmab(d2[3], al, bh[2], bh[3]);
                }
            }
            __syncthreads();
            // d = leaky(D2 + b23) -> bf16 in place
            {
                #pragma unroll
                for (int nt = 0; nt < 4; ++nt) {
                    int j = n0 + nt * 8 + q4 * 2;
                    float bm0 = s->b23s[j], bm1 = s->b23s[j + 1];
                    float x0 = leaky(d2[nt][0] + bm0);
                    float x1 = leaky(d2[nt][1] + bm1);
                    float x2 = leaky(d2[nt][2] + bm0);
                    float x3 = leaky(d2[nt][3] + bm1);
                    u32 hi, lo;
                    split2(x0, x1, hi, lo);
                    *(u32*)((char*)s->Ah + (rlo * SH + j) * 2) = hi;
                    *(u32*)((char*)s->Al + (rlo * SH + j) * 2) = lo;
                    split2(x2, x3, hi, lo);
                    *(u32*)((char*)s->Ah + (rhi * SH + j) * 2) = hi;
                    *(u32*)((char*)s->Al + (rhi * SH + j) * 2) = lo;
                }
            }
            __syncthreads();
            // D5 = d @ ssc (K=64)
            float d5[2][4] = {};
            {
                const u32 aHh = sAh + aoffH, aHl = sAl + aoffH;
                #pragma unroll
                for (int kt = 0; kt < 4; ++kt) {
                    const u32 ka = kt * 32;
                    u32 ah[4], al[4], bh[4], bl[4];
                    ldsm4(ah, aHh + ka); ldsm4(al, aHl + ka);
                    if (nh == 0) {
                        ldsm4(bh, b5h + ka); ldsm4(bl, b5l + ka);
                        mmab(d5[0], ah, bh[0], bh[1]); mmab(d5[1], ah, bh[2], bh[3]);
                        mmab(d5[0], ah, bl[0], bl[1]); mmab(d5[1], ah, bl[2], bl[3]);
                        mmab(d5[0], al, bh[0], bh[1]); mmab(d5[1], al, bh[2], bh[3]);
                    } else {
                        ldsm2(bh, b5h + ka); ldsm2(bl, b5l + ka);
                        mmab(d5[0], ah, bh[0], bh[1]);
                        mmab(d5[0], ah, bl[0], bl[1]);
                        mmab(d5[0], al, bh[0], bh[1]);
                    }
                }
            }
            {
                const int vlo = s->vidx[rlo], vhi = s->vidx[rhi];
                if (nh == 0) {
                    #pragma unroll
                    for (int nt = 0; nt < 2; ++nt) {
                        int k = nt * 8 + q4 * 2;
                        out[(size_t)k       * NVOX + vlo] = d5[nt][0] + s->sscbs[k];
                        out[(size_t)(k + 1) * NVOX + vlo] = d5[nt][1] + s->sscbs[k + 1];
                        out[(size_t)k       * NVOX + vhi] = d5[nt][2] + s->sscbs[k];
                        out[(size_t)(k + 1) * NVOX + vhi] = d5[nt][3] + s->sscbs[k + 1];
                    }
                } else {
                    int k = 16 + q4 * 2;
                    if (k < K_OUT) {
                        out[(size_t)k       * NVOX + vlo] = d5[0][0] + s->sscbs[k];
                        out[(size_t)(k + 1) * NVOX + vlo] = d5[0][1] + s->sscbs[k + 1];
                        out[(size_t)k       * NVOX + vhi] = d5[0][2] + s->sscbs[k];
                        out[(size_t)(k + 1) * NVOX + vhi] = d5[0][3] + s->sscbs[k + 1];
                    }
                }
            }
        }
    } else {
        // ================= UNMASKED ROLE =================
        SmemU* s = reinterpret_cast<SmemU*>(smem_raw);
        for (int i = t; i < 24 * SA; i += THREADS) { s->B4h[i] = 0; s->B4l[i] = 0; }
        for (int i = t; i < 24 * SH; i += THREADS) { s->B5h[i] = 0; s->B5l[i] = 0; }
        __syncthreads();
        for (int i = t; i < 64 * 128; i += THREADS) {
            int j = i & 63, c = i >> 6;
            float x = sdb_w[c * C_HID + j];
            u16 h = f2bf(x); s->B3h[j * SA + c] = h; s->B3l[j * SA + c] = f2bf(x - bf2f(h));
        }
        for (int i = t; i < K_OUT * 128; i += THREADS) {
            int k = i % K_OUT, c = i / K_OUT;
            float x = aux_w[c * K_OUT + k];
            u16 h = f2bf(x); s->B4h[k * SA + c] = h; s->B4l[k * SA + c] = f2bf(x - bf2f(h));
        }
        for (int i = t; i < 64 * K_OUT; i += THREADS) {
            int k = i % K_OUT, j = i / K_OUT;
            float x = ssc_w[j * K_OUT + k];
            u16 h = f2bf(x); s->B5h[k * SH + j] = h; s->B5l[k * SH + j] = f2bf(x - bf2f(h));
        }
        if (t < C_HID) s->sdbbs[t] = sdb_b[t];
        if (t < 24) { s->sscbs[t] = (t < K_OUT) ? ssc_b[t] : 0.f;
                      s->auxbs[t] = (t < K_OUT) ? aux_b[t] : 0.f; }

        const u32 sAh = smem_u32(s->Ah), sAl = smem_u32(s->Al);
        const u32 sB3h = smem_u32(s->B3h), sB3l = smem_u32(s->B3l);
        const u32 sB4h = smem_u32(s->B4h), sB4l = smem_u32(s->B4l);
        const u32 sB5h = smem_u32(s->B5h), sB5l = smem_u32(s->B5l);
        const u32 b3h0 = sB3h + BOFF(n0, SA), b3h1 = sB3h + BOFF(n0 + 16, SA);
        const u32 b3l0 = sB3l + BOFF(n0, SA), b3l1 = sB3l + BOFF(n0 + 16, SA);
        const u32 ox2 = (u32)(((16 + rw) * SA + (qd & 1) * 8) * 2);
        const u32 b4h = nh ? (sB4h + ox2) : (sB4h + BOFF(0, SA));
        const u32 b4l = nh ? (sB4l + ox2) : (sB4l + BOFF(0, SA));
        const u32 ox2H = (u32)(((16 + rw) * SH + (qd & 1) * 8) * 2);
        const u32 b5h = nh ? (sB5h + ox2H) : (sB5h + BOFF(0, SH));
        const u32 b5l = nh ? (sB5l + ox2H) : (sB5l + BOFF(0, SH));

        for (;;) {
            __syncthreads();
            if (t == 0) s->nxt = atomicAdd(&g_uctr, 1);
            __syncthreads();
            const int tile = s->nxt;
            if (tile >= UT) break;
            const int* idxs = ui + tile * TILE;
            {
                const int gv = __ldg(&idxs[lv]);
                #pragma unroll 4
                for (int i = 0; i < 16; ++i) {
                    int c = i * 8 + lcq;
                    float f0 = x3d[(size_t)c * NVOX + gv];
                    float f1 = x3d[(size_t)(c + 1) * NVOX + gv];
                    u32 hi, lo; split2(f0, f1, hi, lo);
                    *(u32*)((char*)s->Ah + (lv * SA + c) * 2) = hi;
                    *(u32*)((char*)s->Al + (lv * SA + c) * 2) = lo;
                }
            }
            if (t < TILE) s->vidx[t] = idxs[t];
            __syncthreads();

            // D3 = feats @ sdb, D4 = feats @ aux (K=128)
            float d3[4][4] = {}, d4[2][4] = {};
            {
                const u32 aAh = sAh + aoffA, aAl = sAl + aoffA;
                #pragma unroll
                for (int kt = 0; kt < 8; ++kt) {
                    const u32 ka = kt * 32;
                    u32 ah[4], al[4], bh[4], bl[4];
                    ldsm4(ah, aAh + ka); ldsm4(al, aAl + ka);
                    ldsm4(bh, b3h0 + ka); ldsm4(bl, b3l0 + ka);
                    mmab(d3[0], ah, bh[0], bh[1]); mmab(d3[1], ah, bh[2], bh[3]);
                    mmab(d3[0], ah, bl[0], bl[1]); mmab(d3[1], ah, bl[2], bl[3]);
                    mmab(d3[0], al, bh[0], bh[1]); mmab(d3[1], al, bh[2], bh[3]);
                    ldsm4(bh, b3h1 + ka); ldsm4(bl, b3l1 + ka);
                    mmab(d3[2], ah, bh[0], bh[1]); mmab(d3[3], ah, bh[2], bh[3]);
                    mmab(d3[2], ah, bl[0], bl[1]); mmab(d3[3], ah, bl[2], bl[3]);
                    mmab(d3[2], al, bh[0], bh[1]); mmab(d3[3], al, bh[2], bh[3]);
                    if (nh == 0) {
                        ldsm4(bh, b4h + ka); ldsm4(bl, b4l + ka);
                        mmab(d4[0], ah, bh[0], bh[1]); mmab(d4[1], ah, bh[2], bh[3]);
                        mmab(d4[0], ah, bl[0], bl[1]); mmab(d4[1], ah, bl[2], bl[3]);
                        mmab(d4[0], al, bh[0], bh[1]); mmab(d4[1], al, bh[2], bh[3]);
                    } else {
                        ldsm2(bh, b4h + ka); ldsm2(bl, b4l + ka);
                        mmab(d4[0], ah, bh[0], bh[1]);
                        mmab(d4[0], ah, bl[0], bl[1]);
                        mmab(d4[0], al, bh[0], bh[1]);
                    }
                }
            }
            // AUX writeback: rank = tile*64 + row
            {
                const int rbase = tile * TILE;
                int r0v = rbase + rlo, r1v = rbase + rhi;
                if (nh == 0) {
                    #pragma unroll
                    for (int nt = 0; nt < 2; ++nt) {
                        int k = nt * 8 + q4 * 2;
                        *(float2*)&outsem[(size_t)r0v * K_OUT + k] =
                            make_float2(d4[nt][0] + s->auxbs[k], d4[nt][1] + s->auxbs[k + 1]);
                        *(float2*)&outsem[(size_t)r1v * K_OUT + k] =
                            make_float2(d4[nt][2] + s->auxbs[k], d4[nt][3] + s->auxbs[k + 1]);
                    }
                } else {
                    int k = 16 + q4 * 2;
                    if (k < K_OUT) {
                        *(float2*)&outsem[(size_t)r0v * K_OUT + k] =
                            make_float2(d4[0][0] + s->auxbs[k], d4[0][1] + s->auxbs[k + 1]);
                        *(float2*)&outsem[(size_t)r1v * K_OUT + k] =
                            make_float2(d4[0][2] + s->auxbs[k], d4[0][3] + s->auxbs[k + 1]);
                    }
                }
            }
            __syncthreads();                // feats(SA) reads done before SH overwrite
            // d = leaky(D3 + sdb_b) -> bf16 in place
            {
                #pragma unroll
                for (int nt = 0; nt < 4; ++nt) {
                    int j = n0 + nt * 8 + q4 * 2;
                    float bu0 = s->sdbbs[j], bu1 = s->sdbbs[j + 1];
                    float x0 = leaky(d3[nt][0] + bu0);
                    float x1 = leaky(d3[nt][1] + bu1);
                    float x2 = leaky(d3[nt][2] + bu0);
                    float x3 = leaky(d3[nt][3] + bu1);
                    u32 hi, lo;
                    split2(x0, x1, hi, lo);
                    *(u32*)((char*)s->Ah + (rlo * SH + j) * 2) = hi;
                    *(u32*)((char*)s->Al + (rlo * SH + j) * 2) = lo;
                    split2(x2, x3, hi, lo);
                    *(u32*)((char*)s->Ah + (rhi * SH + j) * 2) = hi;
                    *(u32*)((char*)s->Al + (rhi * SH + j) * 2) = lo;
                }
            }
            __syncthreads();
            // D5 = d @ ssc (K=64)
            float d5[2][4] = {};
            {
                const u32 aHh = sAh + aoffH, aHl = sAl + aoffH;
                #pragma unroll
                for (int kt = 0; kt < 4; ++kt) {
                    const u32 ka = kt * 32;
                    u32 ah[4], al[4], bh[4], bl[4];
                    ldsm4(ah, aHh + ka); ldsm4(al, aHl + ka);
                    if (nh == 0) {
                        ldsm4(bh, b5h + ka); ldsm4(bl, b5l + ka);
                        mmab(d5[0], ah, bh[0], bh[1]); mmab(d5[1], ah, bh[2], bh[3]);
                        mmab(d5[0], ah, bl[0], bl[1]); mmab(d5[1], ah, bl[2], bl[3]);
                        mmab(d5[0], al, bh[0], bh[1]); mmab(d5[1], al, bh[2], bh[3]);
                    } else {
                        ldsm2(bh, b5h + ka); ldsm2(bl, b5l + ka);
                        mmab(d5[0], ah, bh[0], bh[1]);
                        mmab(d5[0], ah, bl[0], bl[1]);
                        mmab(d5[0], al, bh[0], bh[1]);
                    }
                }
            }
            {
                const int vlo = s->vidx[rlo], vhi = s->vidx[rhi];
                if (nh == 0) {
                    #pragma unroll
                    for (int nt = 0; nt < 2; ++nt) {
                        int k = nt * 8 + q4 * 2;
                        out[(size_t)k       * NVOX + vlo] = d5[nt][0] + s->sscbs[k];
                        out[(size_t)(k + 1) * NVOX + vlo] = d5[nt][1] + s->sscbs[k + 1];
                        out[(size_t)k       * NVOX + vhi] = d5[nt][2] + s->sscbs[k];
                        out[(size_t)(k + 1) * NVOX + vhi] = d5[nt][3] + s->sscbs[k + 1];
                    }
                } else {
                    int k = 16 + q4 * 2;
                    if (k < K_OUT) {
                        out[(size_t)k       * NVOX + vlo] = d5[0][0] + s->sscbs[k];
                        out[(size_t)(k + 1) * NVOX + vlo] = d5[0][1] + s->sscbs[k + 1];
                        out[(size_t)k       * NVOX + vhi] = d5[0][2] + s->sscbs[k];
                        out[(size_t)(k + 1) * NVOX + vhi] = d5[0][3] + s->sscbs[k + 1];
                    }
                }
            }
        }
    }
}

extern "C" void kernel_launch(void* const* d_in, const int* in_sizes, int n_in,
                              void* d_out, int out_size)
{
    const float* x3d   = (const float*)d_in[0];
    const float* w1    = (const float*)d_in[1];
    const float* b1    = (const float*)d_in[2];
    const float* ln_g  = (const float*)d_in[3];
    const float* ln_b  = (const float*)d_in[4];
    const float* w2    = (const float*)d_in[5];
    const float* b2    = (const float*)d_in[6];
    const float* sdb_w = (const float*)d_in[7];
    const float* sdb_b = (const float*)d_in[8];
    const float* ssc_w = (const float*)d_in[9];
    const float* ssc_b = (const float*)d_in[10];
    const float* aux_w = (const float*)d_in[11];
    const float* aux_b = (const float*)d_in[12];
    const int* ui      = (const int*)d_in[13];
    const int* mi      = (const int*)d_in[14];
    float* out         = (float*)d_out;

    int nsm = 0;
    cudaDeviceGetAttribute(&nsm, cudaDevAttrMultiProcessorCount, 0);
    if (nsm <= 0) nsm = 148;

    int blocks  = 2 * nsm;
    int mblocks = (blocks * 3) / 4;       // 3:1 masked:unmasked tile ratio

    cudaFuncSetAttribute(fused_kernel,
                         cudaFuncAttributeMaxDynamicSharedMemorySize, SMEM_MAX);

    w23_kernel<<<16, 256>>>(w2, sdb_w, b2, sdb_b);
    fused_kernel<<<blocks, THREADS, SMEM_MAX>>>(x3d, w1, b1, ln_g, ln_b,
                                                sdb_w, sdb_b, ssc_w, ssc_b,
                                                aux_w, aux_b, ui, mi, out, mblocks);
}

// round 17
// speedup vs baseline: 1.3989x; 1.0586x over previous
#include <cuda_runtime.h>
#include <cuda_bf16.h>

#define NVOX   262144
#define NU     65536
#define NM     (NVOX - NU)
#define C_IN   128
#define C_HID  64
#define K_OUT  20
#define PT     16                 // voxels per pair-tile
#define MT16   (NM / PT)          // 12288 masked pair-tiles
#define UT16   (NU / PT)          // 4096 unmasked pair-tiles
#define SA     136                // A/B1/B3/B4 row stride (bf16 elems)
#define SH     72                 // H,d / B2,B5 row stride
#define THREADS 256

typedef unsigned int u32;
typedef unsigned short u16;

__device__ __forceinline__ float leaky(float x) {
    return fmaxf(x, 0.f) + 0.01f * fminf(x, 0.f);
}
__device__ __forceinline__ u16 f2bf(float x) {
    return __bfloat16_as_ushort(__float2bfloat16(x));
}
__device__ __forceinline__ float bf2f(u16 b) {
    return __bfloat162float(__ushort_as_bfloat16(b));
}
__device__ __forceinline__ void split2(float x0, float x1, u32& hi, u32& lo) {
    u16 h0 = f2bf(x0), h1 = f2bf(x1);
    u16 l0 = f2bf(x0 - bf2f(h0)), l1 = f2bf(x1 - bf2f(h1));
    hi = (u32)h0 | ((u32)h1 << 16);
    lo = (u32)l0 | ((u32)l1 << 16);
}
__device__ __forceinline__ u32 smem_u32(const void* p) {
    u32 a; asm("{ .reg .u64 t; cvta.to.shared.u64 t, %1; cvt.u32.u64 %0, t; }" : "=r"(a) : "l"(p));
    return a;
}
__device__ __forceinline__ void ldsm4(u32* r, u32 addr) {
    asm volatile("ldmatrix.sync.aligned.m8n8.x4.shared.b16 {%0,%1,%2,%3}, [%4];"
                 : "=r"(r[0]), "=r"(r[1]), "=r"(r[2]), "=r"(r[3]) : "r"(addr));
}
__device__ __forceinline__ void ldsm2(u32* r, u32 addr) {
    asm volatile("ldmatrix.sync.aligned.m8n8.x2.shared.b16 {%0,%1}, [%2];"
                 : "=r"(r[0]), "=r"(r[1]) : "r"(addr));
}
__device__ __forceinline__ void mmab(float* c, const u32* a, u32 b0, u32 b1) {
    asm volatile("mma.sync.aligned.m16n8k16.row.col.f32.bf16.bf16.f32 "
                 "{%0,%1,%2,%3}, {%4,%5,%6,%7}, {%8,%9}, {%0,%1,%2,%3};"
                 : "+f"(c[0]), "+f"(c[1]), "+f"(c[2]), "+f"(c[3])
                 : "r"(a[0]), "r"(a[1]), "r"(a[2]), "r"(a[3]), "r"(b0), "r"(b1));
}

__device__ float g_W23[C_HID * C_HID];
__device__ float g_b23[C_HID];
__device__ int   g_mctr;
__device__ int   g_uctr;

__global__ void w23_kernel(const float* __restrict__ w2, const float* __restrict__ sdb_w,
                           const float* __restrict__ b2, const float* __restrict__ sdb_b) {
    int idx = blockIdx.x * blockDim.x + threadIdx.x;
    if (idx == 0) { g_mctr = 0; g_uctr = 0; }
    if (idx < C_HID * C_HID) {
        int j = idx >> 6, j2 = idx & 63;
        float acc = 0.f;
        #pragma unroll 8
        for (int c = 0; c < C_IN; ++c) acc += w2[j * C_IN + c] * sdb_w[c * C_HID + j2];
        g_W23[idx] = acc;
    }
    if (idx < C_HID) {
        float acc = sdb_b[idx];
        #pragma unroll 8
        for (int c = 0; c < C_IN; ++c) acc += b2[c] * sdb_w[c * C_HID + idx];
        g_b23[idx] = acc;
    }
}

struct __align__(16) Pair {
    u16 Ah[PT * SA], Al[PT * SA];       // feats (SA); later H / d (SH)
    float red1[2 * PT], red2[2 * PT];
    int   vidx[PT];
    int   nxt, pad[3];                  // pad -> sizeof(Pair) % 16 == 0
};
struct SmemM {                          // masked role
    Pair p[4];
    u16 B1h[64 * SA], B1l[64 * SA];     // w1  [j][c]
    u16 B2h[64 * SH], B2l[64 * SH];     // W23 [j2][j]
    u16 B5h[24 * SH], B5l[24 * SH];     // ssc [k][j2]
    float b1s[64], lngs[64], lnbs[64], b23s[64];
    float sscbs[24];
};
struct SmemU {                          // unmasked role
    Pair p[4];
    u16 B3h[64 * SA], B3l[64 * SA];     // sdb [j][c]
    u16 B4h[24 * SA], B4l[24 * SA];     // aux [k][c]
    u16 B5h[24 * SH], B5l[24 * SH];     // ssc [k][j2]
    float sdbbs[64];
    float sscbs[24], auxbs[24];
};
#define SMEM_MAX ((int)(sizeof(SmemM) > sizeof(SmemU) ? sizeof(SmemM) : sizeof(SmemU)))

__global__ void __launch_bounds__(THREADS, 2)
fused_kernel(const float* __restrict__ x3d,
             const float* __restrict__ w1,    const float* __restrict__ b1,
             const float* __restrict__ ln_g,  const float* __restrict__ ln_b,
             const float* __restrict__ sdb_w, const float* __restrict__ sdb_b,
             const float* __restrict__ ssc_w, const float* __restrict__ ssc_b,
             const float* __restrict__ aux_w, const float* __restrict__ aux_b,
             const int* __restrict__ ui,      const int* __restrict__ mi,
             float* __restrict__ out, int mblocks)
{
    extern __shared__ char smem_raw[];
    const int t = threadIdx.x;
    const int warp = t >> 5, lane = t & 31;
    const int pairid = warp >> 1;          // 0..3
    const int nh = warp & 1;               // n-half
    const int t64 = t & 63;
    const int barid = 1 + pairid;
    #define BARP() asm volatile("bar.sync %0, 64;" :: "r"(barid) : "memory")

    const int n0 = nh * 32;
    const int qd = lane >> 3, rw = lane & 7;
    const u32 aoffA = (u32)(((rw + (qd & 1) * 8) * SA + (qd >> 1) * 8) * 2);
    const u32 aoffH = (u32)(((rw + (qd & 1) * 8) * SH + (qd >> 1) * 8) * 2);
    #define BOFF(nb, S) ((u32)((((nb) + rw + (qd >> 1) * 8) * (S) + (qd & 1) * 8) * 2))
    const int rlo = lane >> 2, rhi = rlo + 8;     // rows within pair's 16
    const int q4 = lane & 3;
    // gather mapping: 64 threads -> 16 rows x 128 c (32 c per thread)
    const int grow = t64 >> 2;
    const int gcq  = (t64 & 3) * 32;

    float* outsem = out + (size_t)K_OUT * NVOX;

    if (blockIdx.x < mblocks) {
        // ================= MASKED ROLE =================
        SmemM* s = reinterpret_cast<SmemM*>(smem_raw);
        Pair* p = &s->p[pairid];
        for (int i = t; i < 64 * 128; i += THREADS) {
            int j = i & 63, c = i >> 6;
            float x = w1[c * C_HID + j];
            u16 h = f2bf(x); s->B1h[j * SA + c] = h; s->B1l[j * SA + c] = f2bf(x - bf2f(h));
        }
        for (int i = t; i < 64 * 64; i += THREADS) {
            int j2 = i & 63, j = i >> 6;
            float x = g_W23[j * C_HID + j2];
            u16 h = f2bf(x); s->B2h[j2 * SH + j] = h; s->B2l[j2 * SH + j] = f2bf(x - bf2f(h));
        }
        for (int i = t; i < 24 * SH; i += THREADS) { s->B5h[i] = 0; s->B5l[i] = 0; }
        __syncthreads();
        for (int i = t; i < 64 * K_OUT; i += THREADS) {
            int k = i % K_OUT, j = i / K_OUT;
            float x = ssc_w[j * K_OUT + k];
            u16 h = f2bf(x); s->B5h[k * SH + j] = h; s->B5l[k * SH + j] = f2bf(x - bf2f(h));
        }
        if (t < C_HID) {
            s->b1s[t] = b1[t]; s->lngs[t] = ln_g[t]; s->lnbs[t] = ln_b[t]; s->b23s[t] = g_b23[t];
        }
        if (t < 24) s->sscbs[t] = (t < K_OUT) ? ssc_b[t] : 0.f;
        __syncthreads();

        const u32 sAh = smem_u32(p->Ah), sAl = smem_u32(p->Al);
        const u32 sB1h = smem_u32(s->B1h), sB1l = smem_u32(s->B1l);
        const u32 sB2h = smem_u32(s->B2h), sB2l = smem_u32(s->B2l);
        const u32 sB5h = smem_u32(s->B5h), sB5l = smem_u32(s->B5l);
        const u32 b1h0 = sB1h + BOFF(n0, SA), b1h1 = sB1h + BOFF(n0 + 16, SA);
        const u32 b1l0 = sB1l + BOFF(n0, SA), b1l1 = sB1l + BOFF(n0 + 16, SA);
        const u32 b2h0 = sB2h + BOFF(n0, SH), b2h1 = sB2h + BOFF(n0 + 16, SH);
        const u32 b2l0 = sB2l + BOFF(n0, SH), b2l1 = sB2l + BOFF(n0 + 16, SH);
        const u32 ox2H = (u32)(((16 + rw) * SH + (qd & 1) * 8) * 2);
        const u32 b5h = nh ? (sB5h + ox2H) : (sB5h + BOFF(0, SH));
        const u32 b5l = nh ? (sB5l + ox2H) : (sB5l + BOFF(0, SH));

        for (;;) {
            BARP();                        // prior tile consumed; protects nxt
            if (t64 == 0) p->nxt = atomicAdd(&g_mctr, 1);
            BARP();
            const int tile = p->nxt;
            if (tile >= MT16) break;
            const int* idxs = mi + tile * PT;
            {
                const int gv = __ldg(&idxs[grow]);
                if ((t64 & 3) == 0) p->vidx[grow] = gv;
                #pragma unroll 4
                for (int i = 0; i < 16; ++i) {
                    int c = gcq + i * 2;
                    float f0 = x3d[(size_t)c * NVOX + gv];
                    float f1 = x3d[(size_t)(c + 1) * NVOX + gv];
                    u32 hi, lo; split2(f0, f1, hi, lo);
                    *(u32*)((char*)p->Ah + (grow * SA + c) * 2) = hi;
                    *(u32*)((char*)p->Al + (grow * SA + c) * 2) = lo;
                }
            }
            BARP();

            // D1 = feats @ w1 (K=128)
            float d1[4][4] = {};
            {
                const u32 aAh = sAh + aoffA, aAl = sAl + aoffA;
                #pragma unroll
                for (int kt = 0; kt < 8; ++kt) {
                    const u32 ka = kt * 32;
                    u32 ah[4], al[4], bh[4], bl[4];
                    ldsm4(ah, aAh + ka); ldsm4(al, aAl + ka);
                    ldsm4(bh, b1h0 + ka); ldsm4(bl, b1l0 + ka);
                    mmab(d1[0], ah, bh[0], bh[1]); mmab(d1[1], ah, bh[2], bh[3]);
                    mmab(d1[0], ah, bl[0], bl[1]); mmab(d1[1], ah, bl[2], bl[3]);
                    mmab(d1[0], al, bh[0], bh[1]); mmab(d1[1], al, bh[2], bh[3]);
                    ldsm4(bh, b1h1 + ka); ldsm4(bl, b1l1 + ka);
                    mmab(d1[2], ah, bh[0], bh[1]); mmab(d1[3], ah, bh[2], bh[3]);
                    mmab(d1[2], ah, bl[0], bl[1]); mmab(d1[3], ah, bl[2], bl[3]);
                    mmab(d1[2], al, bh[0], bh[1]); mmab(d1[3], al, bh[2], bh[3]);
                }
            }
            // h = D1 + b1; LN partials over this warp's 32 j
            {
                float slo = 0.f, qlo = 0.f, shi = 0.f, qhi = 0.f;
                #pragma unroll
                for (int nt = 0; nt < 4; ++nt) {
                    int j = n0 + nt * 8 + q4 * 2;
                    float bb0 = s->b1s[j], bb1 = s->b1s[j + 1];
                    d1[nt][0] += bb0; d1[nt][1] += bb1; d1[nt][2] += bb0; d1[nt][3] += bb1;
                    slo += d1[nt][0] + d1[nt][1];
                    qlo += d1[nt][0] * d1[nt][0] + d1[nt][1] * d1[nt][1];
                    shi += d1[nt][2] + d1[nt][3];
                    qhi += d1[nt][2] * d1[nt][2] + d1[nt][3] * d1[nt][3];
                }
                #pragma unroll
                for (int o = 1; o < 4; o <<= 1) {
                    slo += __shfl_xor_sync(0xFFFFFFFFu, slo, o);
                    qlo += __shfl_xor_sync(0xFFFFFFFFu, qlo, o);
                    shi += __shfl_xor_sync(0xFFFFFFFFu, shi, o);
                    qhi += __shfl_xor_sync(0xFFFFFFFFu, qhi, o);
                }
                if (q4 == 0) {
                    p->red1[nh * PT + rlo] = slo; p->red2[nh * PT + rlo] = qlo;
                    p->red1[nh * PT + rhi] = shi; p->red2[nh * PT + rhi] = qhi;
                }
            }
            BARP();
            // per-thread LN constants + normalize + leaky -> H (SH)
            {
                float su0 = p->red1[rlo] + p->red1[PT + rlo];
                float sq0 = p->red2[rlo] + p->red2[PT + rlo];
                float su1 = p->red1[rhi] + p->red1[PT + rhi];
                float sq1 = p->red2[rhi] + p->red2[PT + rhi];
                float mu0 = su0 * (1.f / 64.f), mu1 = su1 * (1.f / 64.f);
                float rs0 = rsqrtf(sq0 * (1.f / 64.f) - mu0 * mu0 + 1e-5f);
                float rs1 = rsqrtf(sq1 * (1.f / 64.f) - mu1 * mu1 + 1e-5f);
                #pragma unroll
                for (int nt = 0; nt < 4; ++nt) {
                    int j = n0 + nt * 8 + q4 * 2;
                    float g0 = s->lngs[j], g1 = s->lngs[j + 1];
                    float c0 = s->lnbs[j], c1 = s->lnbs[j + 1];
                    float x0 = leaky((d1[nt][0] - mu0) * rs0 * g0 + c0);
                    float x1 = leaky((d1[nt][1] - mu0) * rs0 * g1 + c1);
                    float x2 = leaky((d1[nt][2] - mu1) * rs1 * g0 + c0);
                    float x3 = leaky((d1[nt][3] - mu1) * rs1 * g1 + c1);
                    u32 hi, lo;
                    split2(x0, x1, hi, lo);
                    *(u32*)((char*)p->Ah + (rlo * SH + j) * 2) = hi;
                    *(u32*)((char*)p->Al + (rlo * SH + j) * 2) = lo;
                    split2(x2, x3, hi, lo);
                    *(u32*)((char*)p->Ah + (rhi * SH + j) * 2) = hi;
                    *(u32*)((char*)p->Al + (rhi * SH + j) * 2) = lo;
                }
            }
            BARP();
            // D2 = H @ W23 (K=64)
            float d2[4][4] = {};
            {
                const u32 aHh = sAh + aoffH, aHl = sAl + aoffH;
                #pragma unroll
                for (int kt = 0; kt < 4; ++kt) {
                    const u32 ka = kt * 32;
                    u32 ah[4], al[4], bh[4], bl[4];
                    ldsm4(ah, aHh + ka); ldsm4(al, aHl + ka);
                    ldsm4(bh, b2h0 + ka); ldsm4(bl, b2l0 + ka);
                    mmab(d2[0], ah, bh[0], bh[1]); mmab(d2[1], ah, bh[2], bh[3]);
                    mmab(d2[0], ah, bl[0], bl[1]); mmab(d2[1], ah, bl[2], bl[3]);
                    mmab(d2[0], al, bh[0], bh[1]); mmab(d2[1], al, bh[2], bh[3]);
                    ldsm4(bh, b2h1 + ka); ldsm4(bl, b2l1 + ka);
                    mmab(d2[2], ah, bh[0], bh[1]); mmab(d2[3], ah, bh[2], bh[3]);
                    mmab(d2[2], ah, bl[0], bl[1]); mmab(d2[3], ah, bl[2], bl[3]);
                    mmab(d2[2], al, bh[0], bh[1]); mmab(d2[3], al, bh[2], bh[3]);
                }
            }
            BARP();
            // d = leaky(D2 + b23) -> bf16 in place
            {
                #pragma unroll
                for (int nt = 0; nt < 4; ++nt) {
                    int j = n0 + nt * 8 + q4 * 2;
                    float bm0 = s->b23s[j], bm1 = s->b23s[j + 1];
                    float x0 = leaky(d2[nt][0] + bm0);
                    float x1 = leaky(d2[nt][1] + bm1);
                    float x2 = leaky(d2[nt][2] + bm0);
                    float x3 = leaky(d2[nt][3] + bm1);
                    u32 hi, lo;
                    split2(x0, x1, hi, lo);
                    *(u32*)((char*)p->Ah + (rlo * SH + j) * 2) = hi;
                    *(u32*)((char*)p->Al + (rlo * SH + j) * 2) = lo;
                    split2(x2, x3, hi, lo);
                    *(u32*)((char*)p->Ah + (rhi * SH + j) * 2) = hi;
                    *(u32*)((char*)p->Al + (rhi * SH + j) * 2) = lo;
                }
            }
            BARP();
            // D5 = d @ ssc (K=64)
            float d5[2][4] = {};
            {
                const u32 aHh = sAh + aoffH, aHl = sAl + aoffH;
                #pragma unroll
                for (int kt = 0; kt < 4; ++kt) {
                    const u32 ka = kt * 32;
                    u32 ah[4], al[4], bh[4], bl[4];
                    ldsm4(ah, aHh + ka); ldsm4(al, aHl + ka);
                    if (nh == 0) {
                        ldsm4(bh, b5h + ka); ldsm4(bl, b5l + ka);
                        mmab(d5[0], ah, bh[0], bh[1]); mmab(d5[1], ah, bh[2], bh[3]);
                        mmab(d5[0], ah, bl[0], bl[1]); mmab(d5[1], ah, bl[2], bl[3]);
                        mmab(d5[0], al, bh[0], bh[1]); mmab(d5[1], al, bh[2], bh[3]);
                    } else {
                        ldsm2(bh, b5h + ka); ldsm2(bl, b5l + ka);
                        mmab(d5[0], ah, bh[0], bh[1]);
                        mmab(d5[0], ah, bl[0], bl[1]);
                        mmab(d5[0], al, bh[0], bh[1]);
                    }
                }
            }
            {
                const int vlo = p->vidx[rlo], vhi = p->vidx[rhi];
                if (nh == 0) {
                    #pragma unroll
                    for (int nt = 0; nt < 2; ++nt) {
                        int k = nt * 8 + q4 * 2;
                        out[(size_t)k       * NVOX + vlo] = d5[nt][0] + s->sscbs[k];
                        out[(size_t)(k + 1) * NVOX + vlo] = d5[nt][1] + s->sscbs[k + 1];
                        out[(size_t)k       * NVOX + vhi] = d5[nt][2] + s->sscbs[k];
                        out[(size_t)(k + 1) * NVOX + vhi] = d5[nt][3] + s->sscbs[k + 1];
                    }
                } else {
                    int k = 16 + q4 * 2;
                    if (k < K_OUT) {
                        out[(size_t)k       * NVOX + vlo] = d5[0][0] + s->sscbs[k];
                        out[(size_t)(k + 1) * NVOX + vlo] = d5[0][1] + s->sscbs[k + 1];
                        out[(size_t)k       * NVOX + vhi] = d5[0][2] + s->sscbs[k];
                        out[(size_t)(k + 1) * NVOX + vhi] = d5[0][3] + s->sscbs[k + 1];
                    }
                }
            }
        }
    } else {
        // ================= UNMASKED ROLE =================
        SmemU* s = reinterpret_cast<SmemU*>(smem_raw);
        Pair* p = &s->p[pairid];
        for (int i = t; i < 24 * SA; i += THREADS) { s->B4h[i] = 0; s->B4l[i] = 0; }
        for (int i = t; i < 24 * SH; i += THREADS) { s->B5h[i] = 0; s->B5l[i] = 0; }
        __syncthreads();
        for (int i = t; i < 64 * 128; i += THREADS) {
            int j = i & 63, c = i >> 6;
            float x = sdb_w[c * C_HID + j];
            u16 h = f2bf(x); s->B3h[j * SA + c] = h; s->B3l[j * SA + c] = f2bf(x - bf2f(h));
        }
        for (int i = t; i < K_OUT * 128; i += THREADS) {
            int k = i % K_OUT, c = i / K_OUT;
            float x = aux_w[c * K_OUT + k];
            u16 h = f2bf(x); s->B4h[k * SA + c] = h; s->B4l[k * SA + c] = f2bf(x - bf2f(h));
        }
        for (int i = t; i < 64 * K_OUT; i += THREADS) {
            int k = i % K_OUT, j = i / K_OUT;
            float x = ssc_w[j * K_OUT + k];
            u16 h = f2bf(x); s->B5h[k * SH + j] = h; s->B5l[k * SH + j] = f2bf(x - bf2f(h));
        }
        if (t < C_HID) s->sdbbs[t] = sdb_b[t];
        if (t < 24) { s->sscbs[t] = (t < K_OUT) ? ssc_b[t] : 0.f;
                      s->auxbs[t] = (t < K_OUT) ? aux_b[t] : 0.f; }
        __syncthreads();

        const u32 sAh = smem_u32(p->Ah), sAl = smem_u32(p->Al);
        const u32 sB3h = smem_u32(s->B3h), sB3l = smem_u32(s->B3l);
        const u32 sB4h = smem_u32(s->B4h), sB4l = smem_u32(s->B4l);
        const u32 sB5h = smem_u32(s->B5h), sB5l = smem_u32(s->B5l);
        const u32 b3h0 = sB3h + BOFF(n0, SA), b3h1 = sB3h + BOFF(n0 + 16, SA);
        const u32 b3l0 = sB3l + BOFF(n0, SA), b3l1 = sB3l + BOFF(n0 + 16, SA);
        const u32 ox2 = (u32)(((16 + rw) * SA + (qd & 1) * 8) * 2);
        const u32 b4h = nh ? (sB4h + ox2) : (sB4h + BOFF(0, SA));
        const u32 b4l = nh ? (sB4l + ox2) : (sB4l + BOFF(0, SA));
        const u32 ox2H = (u32)(((16 + rw) * SH + (qd & 1) * 8) * 2);
        const u32 b5h = nh ? (sB5h + ox2H) : (sB5h + BOFF(0, SH));
        const u32 b5l = nh ? (sB5l + ox2H) : (sB5l + BOFF(0, SH));

        for (;;) {
            BARP();
            if (t64 == 0) p->nxt = atomicAdd(&g_uctr, 1);
            BARP();
            const int tile = p->nxt;
            if (tile >= UT16) break;
            const int* idxs = ui + tile * PT;
            {
                const int gv = __ldg(&idxs[grow]);
                if ((t64 & 3) == 0) p->vidx[grow] = gv;
                #pragma unroll 4
                for (int i = 0; i < 16; ++i) {
                    int c = gcq + i * 2;
                    float f0 = x3d[(size_t)c * NVOX + gv];
                    float f1 = x3d[(size_t)(c + 1) * NVOX + gv];
                    u32 hi, lo; split2(f0, f1, hi, lo);
                    *(u32*)((char*)p->Ah + (grow * SA + c) * 2) = hi;
                    *(u32*)((char*)p->Al + (grow * SA + c) * 2) = lo;
                }
            }
            BARP();

            // D3 = feats @ sdb, D4 = feats @ aux (K=128)
            float d3[4][4] = {}, d4[2][4] = {};
            {
                const u32 aAh = sAh + aoffA, aAl = sAl + aoffA;
                #pragma unroll
                for (int kt = 0; kt < 8; ++kt) {
                    const u32 ka = kt * 32;
                    u32 ah[4], al[4], bh[4], bl[4];
                    ldsm4(ah, aAh + ka); ldsm4(al, aAl + ka);
                    ldsm4(bh, b3h0 + ka); ldsm4(bl, b3l0 + ka);
                    mmab(d3[0], ah, bh[0], bh[1]); mmab(d3[1], ah, bh[2], bh[3]);
                    mmab(d3[0], ah, bl[0], bl[1]); mmab(d3[1], ah, bl[2], bl[3]);
                    mmab(d3[0], al, bh[0], bh[1]); mmab(d3[1], al, bh[2], bh[3]);
                    ldsm4(bh, b3h1 + ka); ldsm4(bl, b3l1 + ka);
                    mmab(d3[2], ah, bh[0], bh[1]); mmab(d3[3], ah, bh[2], bh[3]);
                    mmab(d3[2], ah, bl[0], bl[1]); mmab(d3[3], ah, bl[2], bl[3]);
                    mmab(d3[2], al, bh[0], bh[1]); mmab(d3[3], al, bh[2], bh[3]);
                    if (nh == 0) {
                        ldsm4(bh, b4h + ka); ldsm4(bl, b4l + ka);
                        mmab(d4[0], ah, bh[0], bh[1]); mmab(d4[1], ah, bh[2], bh[3]);
                        mmab(d4[0], ah, bl[0], bl[1]); mmab(d4[1], ah, bl[2], bl[3]);
                        mmab(d4[0], al, bh[0], bh[1]); mmab(d4[1], al, bh[2], bh[3]);
                    } else {
                        ldsm2(bh, b4h + ka); ldsm2(bl, b4l + ka);
                        mmab(d4[0], ah, bh[0], bh[1]);
                        mmab(d4[0], ah, bl[0], bl[1]);
                        mmab(d4[0], al, bh[0], bh[1]);
                    }
                }
            }
            // AUX writeback: rank = tile*16 + row
            {
                const int rbase = tile * PT;
                int r0v = rbase + rlo, r1v = rbase + rhi;
                if (nh == 0) {
                    #pragma unroll
                    for (int nt = 0; nt < 2; ++nt) {
                        int k = nt * 8 + q4 * 2;
                        *(float2*)&outsem[(size_t)r0v * K_OUT + k] =
                            make_float2(d4[nt][0] + s->auxbs[k], d4[nt][1] + s->auxbs[k + 1]);
                        *(float2*)&outsem[(size_t)r1v * K_OUT + k] =
                            make_float2(d4[nt][2] + s->auxbs[k], d4[nt][3] + s->auxbs[k + 1]);
                    }
                } else {
                    int k = 16 + q4 * 2;
                    if (k < K_OUT) {
                        *(float2*)&outsem[(size_t)r0v * K_OUT + k] =
                            make_float2(d4[0][0] + s->auxbs[k], d4[0][1] + s->auxbs[k + 1]);
                        *(float2*)&outsem[(size_t)r1v * K_OUT + k] =
                            make_float2(d4[0][2] + s->auxbs[k], d4[0][3] + s->auxbs[k + 1]);
                    }
                }
            }
            BARP();                        // feats(SA) reads done before SH overwrite
            // d = leaky(D3 + sdb_b) -> bf16 in place
            {
                #pragma unroll
                for (int nt = 0; nt < 4; ++nt) {
                    int j = n0 + nt * 8 + q4 * 2;
                    float bu0 = s->sdbbs[j], bu1 = s->sdbbs[j + 1];
                    float x0 = leaky(d3[nt][0] + bu0);
                    float x1 = leaky(d3[nt][1] + bu1);
                    float x2 = leaky(d3[nt][2] + bu0);
                    float x3 = leaky(d3[nt][3] + bu1);
                    u32 hi, lo;
                    split2(x0, x1, hi, lo);
                    *(u32*)((char*)p->Ah + (rlo * SH + j) * 2) = hi;
                    *(u32*)((char*)p->Al + (rlo * SH + j) * 2) = lo;
                    split2(x2, x3, hi, lo);
                    *(u32*)((char*)p->Ah + (rhi * SH + j) * 2) = hi;
                    *(u32*)((char*)p->Al + (rhi * SH + j) * 2) = lo;
                }
            }
            BARP();
            // D5 = d @ ssc (K=64)
            float d5[2][4] = {};
            {
                const u32 aHh = sAh + aoffH, aHl = sAl + aoffH;
                #pragma unroll
                for (int kt = 0; kt < 4; ++kt) {
                    const u32 ka = kt * 32;
                    u32 ah[4], al[4], bh[4], bl[4];
                    ldsm4(ah, aHh + ka); ldsm4(al, aHl + ka);
                    if (nh == 0) {
                        ldsm4(bh, b5h + ka); ldsm4(bl, b5l + ka);
                        mmab(d5[0], ah, bh[0], bh[1]); mmab(d5[1], ah, bh[2], bh[3]);
                        mmab(d5[0], ah, bl[0], bl[1]); mmab(d5[1], ah, bl[2], bl[3]);
                        mmab(d5[0], al, bh[0], bh[1]); mmab(d5[1], al, bh[2], bh[3]);
                    } else {
                        ldsm2(bh, b5h + ka); ldsm2(bl, b5l + ka);
                        mmab(d5[0], ah, bh[0], bh[1]);
                        mmab(d5[0], ah, bl[0], bl[1]);
                        mmab(d5[0], al, bh[0], bh[1]);
                    }
                }
            }
            {
                const int vlo = p->vidx[rlo], vhi = p->vidx[rhi];
                if (nh == 0) {
                    #pragma unroll
                    for (int nt = 0; nt < 2; ++nt) {
                        int k = nt * 8 + q4 * 2;
                        out[(size_t)k       * NVOX + vlo] = d5[nt][0] + s->sscbs[k];
                        out[(size_t)(k + 1) * NVOX + vlo] = d5[nt][1] + s->sscbs[k + 1];
                        out[(size_t)k       * NVOX + vhi] = d5[nt][2] + s->sscbs[k];
                        out[(size_t)(k + 1) * NVOX + vhi] = d5[nt][3] + s->sscbs[k + 1];
                    }
                } else {
                    int k = 16 + q4 * 2;
                    if (k < K_OUT) {
                        out[(size_t)k       * NVOX + vlo] = d5[0][0] + s->sscbs[k];
                        out[(size_t)(k + 1) * NVOX + vlo] = d5[0][1] + s->sscbs[k + 1];
                        out[(size_t)k       * NVOX + vhi] = d5[0][2] + s->sscbs[k];
                        out[(size_t)(k + 1) * NVOX + vhi] = d5[0][3] + s->sscbs[k + 1];
                    }
                }
            }
        }
    }
}

extern "C" void kernel_launch(void* const* d_in, const int* in_sizes, int n_in,
                              void* d_out, int out_size)
{
    const float* x3d   = (const float*)d_in[0];
    const float* w1    = (const float*)d_in[1];
    const float* b1    = (const float*)d_in[2];
    const float* ln_g  = (const float*)d_in[3];
    const float* ln_b  = (const float*)d_in[4];
    const float* w2    = (const float*)d_in[5];
    const float* b2    = (const float*)d_in[6];
    const float* sdb_w = (const float*)d_in[7];
    const float* sdb_b = (const float*)d_in[8];
    const float* ssc_w = (const float*)d_in[9];
    const float* ssc_b = (const float*)d_in[10];
    const float* aux_w = (const float*)d_in[11];
    const float* aux_b = (const float*)d_in[12];
    const int* ui      = (const int*)d_in[13];
    const int* mi      = (const int*)d_in[14];
    float* out         = (float*)d_out;

    int nsm = 0;
    cudaDeviceGetAttribute(&nsm, cudaDevAttrMultiProcessorCount, 0);
    if (nsm <= 0) nsm = 148;

    int blocks  = 2 * nsm;
    int mblocks = (blocks * 3) / 4;       // 3:1 masked:unmasked ratio

    cudaFuncSetAttribute(fused_kernel,
                         cudaFuncAttributeMaxDynamicSharedMemorySize, SMEM_MAX);

    w23_kernel<<<16, 256>>>(w2, sdb_w, b2, sdb_b);
    fused_kernel<<<blocks, THREADS, SMEM_MAX>>>(x3d, w1, b1, ln_g, ln_b,
                                                sdb_w, sdb_b, ssc_w, ssc_b,
                                                aux_w, aux_b, ui, mi, out, mblocks);
}